// round 4
// baseline (speedup 1.0000x reference)
#include <cuda_runtime.h>

// EdgeNet v4: fine-grained work units (2048 blocks x 128 thr) to kill wave
// quantization; partials kept L2-resident (default store policy) so the MLP
// epilogue reads at L2 speed.

#define N_NODES 8192
#define N_EDGES 32768
#define S_SEG   32
#define NODES_PER_SEG (N_NODES / S_SEG)      // 256
#define E4      (N_EDGES / 4)                // 8192 float4 columns
#define A_THREADS 128
#define EGRPS   (E4 / A_THREADS)             // 64 edge-group blocks
#define NHID    100
#define M_THREADS 128

// Per (segment, edge): bo(float4), bi(float4).  32*32768*2*16B = 32 MB (fits L2).
__device__ float4 g_partial[(size_t)S_SEG * N_EDGES * 2];

__device__ __forceinline__ void fma4(float4& a, float s, const float4& x) {
    a.x = fmaf(s, x.x, a.x);
    a.y = fmaf(s, x.y, a.y);
    a.z = fmaf(s, x.z, a.z);
    a.w = fmaf(s, x.w, a.w);
}

__global__ __launch_bounds__(A_THREADS)
void edgenet_accum_kernel(const float* __restrict__ X,
                          const float* __restrict__ Ri,
                          const float* __restrict__ Ro)
{
    __shared__ float4 sX[NODES_PER_SEG];   // 4 KB

    const int tid = threadIdx.x;
    const int seg = blockIdx.y;
    const int n0  = seg * NODES_PER_SEG;

    const float4* __restrict__ X4 = (const float4*)X;
    for (int i = tid; i < NODES_PER_SEG; i += A_THREADS)
        sX[i] = X4[n0 + i];
    __syncthreads();

    const int e4 = blockIdx.x * A_THREADS + tid;
    const float4* __restrict__ ro_p = (const float4*)Ro + (size_t)n0 * E4 + e4;
    const float4* __restrict__ ri_p = (const float4*)Ri + (size_t)n0 * E4 + e4;

    float4 ao0 = {0,0,0,0}, ao1 = {0,0,0,0}, ao2 = {0,0,0,0}, ao3 = {0,0,0,0};
    float4 ai0 = {0,0,0,0}, ai1 = {0,0,0,0}, ai2 = {0,0,0,0}, ai3 = {0,0,0,0};

    #pragma unroll 4
    for (int n = 0; n < NODES_PER_SEG; ++n) {
        const float4 ro = __ldcs(&ro_p[(size_t)n * E4]);   // stream-once: evict-first
        const float4 ri = __ldcs(&ri_p[(size_t)n * E4]);
        const float4 x  = sX[n];
        fma4(ao0, ro.x, x);  fma4(ao1, ro.y, x);
        fma4(ao2, ro.z, x);  fma4(ao3, ro.w, x);
        fma4(ai0, ri.x, x);  fma4(ai1, ri.y, x);
        fma4(ai2, ri.z, x);  fma4(ai3, ri.w, x);
    }

    // Default-policy stores: partials stay L2-resident for the epilogue.
    float4* __restrict__ dst = &g_partial[((size_t)seg * N_EDGES + (size_t)e4 * 4) * 2];
    dst[0] = ao0;  dst[1] = ai0;
    dst[2] = ao1;  dst[3] = ai1;
    dst[4] = ao2;  dst[5] = ai2;
    dst[6] = ao3;  dst[7] = ai3;
}

__device__ __forceinline__ void add4(float4& a, const float4& b) {
    a.x += b.x; a.y += b.y; a.z += b.z; a.w += b.w;
}

__device__ __forceinline__ float fast_tanh(float x) {
    float e = __expf(2.0f * x);
    return 1.0f - __fdividef(2.0f, e + 1.0f);
}

__global__ __launch_bounds__(M_THREADS)
void edgenet_mlp_kernel(const float* __restrict__ W1,
                        const float* __restrict__ b1,
                        const float* __restrict__ W2,
                        const float* __restrict__ b2,
                        float* __restrict__ out)
{
    __shared__ __align__(16) float sW1t[NHID][8];   // W1 transposed [j][k]
    __shared__ float sb1[NHID];
    __shared__ float sW2[NHID];

    const int tid = threadIdx.x;
    for (int i = tid; i < 8 * NHID; i += M_THREADS) {
        int k = i / NHID, j = i % NHID;             // W1 is [8,100] row-major
        sW1t[j][k] = W1[i];
    }
    for (int i = tid; i < NHID; i += M_THREADS) {
        sb1[i] = b1[i];
        sW2[i] = W2[i];
    }
    __syncthreads();

    const int e = blockIdx.x * M_THREADS + tid;

    // 4 independent accumulator pairs -> 8 loads in flight per unrolled step.
    float4 aoA = {0,0,0,0}, aiA = {0,0,0,0};
    float4 aoB = {0,0,0,0}, aiB = {0,0,0,0};
    float4 aoC = {0,0,0,0}, aiC = {0,0,0,0};
    float4 aoD = {0,0,0,0}, aiD = {0,0,0,0};
    #pragma unroll
    for (int seg = 0; seg < S_SEG; seg += 4) {
        const float4* pA = &g_partial[((size_t)(seg + 0) * N_EDGES + e) * 2];
        const float4* pB = &g_partial[((size_t)(seg + 1) * N_EDGES + e) * 2];
        const float4* pC = &g_partial[((size_t)(seg + 2) * N_EDGES + e) * 2];
        const float4* pD = &g_partial[((size_t)(seg + 3) * N_EDGES + e) * 2];
        float4 a0 = pA[0], a1 = pA[1];
        float4 b0 = pB[0], b1v = pB[1];
        float4 c0 = pC[0], c1 = pC[1];
        float4 d0 = pD[0], d1 = pD[1];
        add4(aoA, a0);  add4(aiA, a1);
        add4(aoB, b0);  add4(aiB, b1v);
        add4(aoC, c0);  add4(aiC, c1);
        add4(aoD, d0);  add4(aiD, d1);
    }
    add4(aoA, aoB);  add4(aiA, aiB);
    add4(aoC, aoD);  add4(aiC, aiD);
    add4(aoA, aoC);  add4(aiA, aiC);

    float acc = b2[0];
    #pragma unroll 4
    for (int j = 0; j < NHID; ++j) {
        const float4 w0 = *(const float4*)&sW1t[j][0];
        const float4 w1 = *(const float4*)&sW1t[j][4];
        float s = sb1[j];
        s = fmaf(aoA.x, w0.x, s);
        s = fmaf(aoA.y, w0.y, s);
        s = fmaf(aoA.z, w0.z, s);
        s = fmaf(aoA.w, w0.w, s);
        s = fmaf(aiA.x, w1.x, s);
        s = fmaf(aiA.y, w1.y, s);
        s = fmaf(aiA.z, w1.z, s);
        s = fmaf(aiA.w, w1.w, s);
        acc = fmaf(fast_tanh(s), sW2[j], acc);
    }
    out[e] = __fdividef(1.0f, 1.0f + __expf(-acc));
}

extern "C" void kernel_launch(void* const* d_in, const int* in_sizes, int n_in,
                              void* d_out, int out_size)
{
    // metadata order: X, Ri, Ro, W1, b1, W2, b2
    const float* X  = (const float*)d_in[0];
    const float* Ri = (const float*)d_in[1];
    const float* Ro = (const float*)d_in[2];
    const float* W1 = (const float*)d_in[3];
    const float* b1 = (const float*)d_in[4];
    const float* W2 = (const float*)d_in[5];
    const float* b2 = (const float*)d_in[6];
    float* out = (float*)d_out;

    dim3 grid1(EGRPS, S_SEG);              // 64 x 32 = 2048 blocks of 128 thr
    edgenet_accum_kernel<<<grid1, A_THREADS>>>(X, Ri, Ro);

    dim3 grid2(N_EDGES / M_THREADS);       // 256 blocks
    edgenet_mlp_kernel<<<grid2, M_THREADS>>>(W1, b1, W2, b2, out);
}

// round 5
// speedup vs baseline: 1.0256x; 1.0256x over previous
#include <cuda_runtime.h>

// EdgeNet v5: phase-1 = R3 best config (512x256, S_SEG=16, ~6.9 TB/s = HBM
// ceiling). phase-2 rebuilt with 4 threads/edge: parallel segment reduction
// + split MLP via shared-memory combines.

#define N_NODES 8192
#define N_EDGES 32768
#define S_SEG   16
#define NODES_PER_SEG (N_NODES / S_SEG)      // 512
#define E4      (N_EDGES / 4)                // 8192 float4 columns
#define A_THREADS 256
#define EGRPS   (E4 / A_THREADS)             // 32 edge-group blocks
#define NHID    100

#define M_THREADS 256
#define EPB2     64                          // edges per phase-2 block
#define SUBS     4                           // threads per edge
#define SEGS_PER_SUB (S_SEG / SUBS)          // 4

// Per (segment, edge): bo(float4), bi(float4).  16 MB.
__device__ float4 g_partial[(size_t)S_SEG * N_EDGES * 2];

__device__ __forceinline__ void fma4(float4& a, float s, const float4& x) {
    a.x = fmaf(s, x.x, a.x);
    a.y = fmaf(s, x.y, a.y);
    a.z = fmaf(s, x.z, a.z);
    a.w = fmaf(s, x.w, a.w);
}
__device__ __forceinline__ void add4(float4& a, const float4& b) {
    a.x += b.x; a.y += b.y; a.z += b.z; a.w += b.w;
}

__global__ __launch_bounds__(A_THREADS, 4)
void edgenet_accum_kernel(const float* __restrict__ X,
                          const float* __restrict__ Ri,
                          const float* __restrict__ Ro)
{
    __shared__ float4 sX[NODES_PER_SEG];   // 8 KB

    const int tid = threadIdx.x;
    const int seg = blockIdx.y;
    const int n0  = seg * NODES_PER_SEG;

    const float4* __restrict__ X4 = (const float4*)X;
    for (int i = tid; i < NODES_PER_SEG; i += A_THREADS)
        sX[i] = X4[n0 + i];
    __syncthreads();

    const int e4 = blockIdx.x * A_THREADS + tid;
    const float4* __restrict__ ro_p = (const float4*)Ro + (size_t)n0 * E4 + e4;
    const float4* __restrict__ ri_p = (const float4*)Ri + (size_t)n0 * E4 + e4;

    float4 ao0 = {0,0,0,0}, ao1 = {0,0,0,0}, ao2 = {0,0,0,0}, ao3 = {0,0,0,0};
    float4 ai0 = {0,0,0,0}, ai1 = {0,0,0,0}, ai2 = {0,0,0,0}, ai3 = {0,0,0,0};

    #pragma unroll 4
    for (int n = 0; n < NODES_PER_SEG; ++n) {
        const float4 ro = __ldcs(&ro_p[(size_t)n * E4]);   // stream-once
        const float4 ri = __ldcs(&ri_p[(size_t)n * E4]);
        const float4 x  = sX[n];
        fma4(ao0, ro.x, x);  fma4(ao1, ro.y, x);
        fma4(ao2, ro.z, x);  fma4(ao3, ro.w, x);
        fma4(ai0, ri.x, x);  fma4(ai1, ri.y, x);
        fma4(ai2, ri.z, x);  fma4(ai3, ri.w, x);
    }

    float4* __restrict__ dst = &g_partial[((size_t)seg * N_EDGES + (size_t)e4 * 4) * 2];
    dst[0] = ao0;  dst[1] = ai0;
    dst[2] = ao1;  dst[3] = ai1;
    dst[4] = ao2;  dst[5] = ai2;
    dst[6] = ao3;  dst[7] = ai3;
}

__device__ __forceinline__ float fast_tanh(float x) {
    float e = __expf(2.0f * x);
    return 1.0f - __fdividef(2.0f, e + 1.0f);
}

__global__ __launch_bounds__(M_THREADS)
void edgenet_mlp_kernel(const float* __restrict__ W1,
                        const float* __restrict__ b1,
                        const float* __restrict__ W2,
                        const float* __restrict__ b2,
                        float* __restrict__ out)
{
    __shared__ __align__(16) float sW1t[NHID][8];   // W1 transposed [j][k]
    __shared__ float sb1[NHID];
    __shared__ float sW2[NHID];
    __shared__ float sPart[SUBS][EPB2][9];          // padded: 9 coprime w/ 32 banks
    __shared__ float sAcc[SUBS][EPB2];

    const int tid = threadIdx.x;
    for (int i = tid; i < 8 * NHID; i += M_THREADS) {
        int k = i / NHID, j = i % NHID;             // W1 is [8,100] row-major
        sW1t[j][k] = W1[i];
    }
    for (int i = tid; i < NHID; i += M_THREADS) {
        sb1[i] = b1[i];
        sW2[i] = W2[i];
    }

    const int el  = tid & (EPB2 - 1);               // edge within block (coalesced)
    const int sub = tid >> 6;                       // 0..3: which seg quarter
    const int e   = blockIdx.x * EPB2 + el;

    // Each thread reduces 4 segments; warp-coalesced (lanes = consecutive e).
    float4 aoA = {0,0,0,0}, aiA = {0,0,0,0};
    float4 aoB = {0,0,0,0}, aiB = {0,0,0,0};
    #pragma unroll
    for (int s = 0; s < SEGS_PER_SUB; s += 2) {
        const int segA = sub * SEGS_PER_SUB + s;
        const float4* pA = &g_partial[((size_t)segA * N_EDGES + e) * 2];
        const float4* pB = &g_partial[((size_t)(segA + 1) * N_EDGES + e) * 2];
        float4 a0 = pA[0], a1 = pA[1];
        float4 b0 = pB[0], b1v = pB[1];
        add4(aoA, a0);  add4(aiA, a1);
        add4(aoB, b0);  add4(aiB, b1v);
    }
    add4(aoA, aoB);
    add4(aiA, aiB);

    sPart[sub][el][0] = aoA.x;  sPart[sub][el][1] = aoA.y;
    sPart[sub][el][2] = aoA.z;  sPart[sub][el][3] = aoA.w;
    sPart[sub][el][4] = aiA.x;  sPart[sub][el][5] = aiA.y;
    sPart[sub][el][6] = aiA.z;  sPart[sub][el][7] = aiA.w;
    __syncthreads();

    // All threads rebuild the full 8-float edge feature B[e].
    float B[8];
    #pragma unroll
    for (int f = 0; f < 8; ++f)
        B[f] = (sPart[0][el][f] + sPart[1][el][f])
             + (sPart[2][el][f] + sPart[3][el][f]);

    // MLP split: thread handles hidden units j = 4k + sub, k = 0..24.
    float acc = 0.0f;
    #pragma unroll 5
    for (int k = 0; k < NHID / SUBS; ++k) {
        const int j = 4 * k + sub;
        const float4 w0 = *(const float4*)&sW1t[j][0];
        const float4 w1 = *(const float4*)&sW1t[j][4];
        float s = sb1[j];
        s = fmaf(B[0], w0.x, s);
        s = fmaf(B[1], w0.y, s);
        s = fmaf(B[2], w0.z, s);
        s = fmaf(B[3], w0.w, s);
        s = fmaf(B[4], w1.x, s);
        s = fmaf(B[5], w1.y, s);
        s = fmaf(B[6], w1.z, s);
        s = fmaf(B[7], w1.w, s);
        acc = fmaf(fast_tanh(s), sW2[j], acc);
    }
    sAcc[sub][el] = acc;
    __syncthreads();

    if (tid < EPB2) {
        float a = b2[0] + (sAcc[0][tid] + sAcc[1][tid])
                        + (sAcc[2][tid] + sAcc[3][tid]);
        out[blockIdx.x * EPB2 + tid] = __fdividef(1.0f, 1.0f + __expf(-a));
    }
}

extern "C" void kernel_launch(void* const* d_in, const int* in_sizes, int n_in,
                              void* d_out, int out_size)
{
    // metadata order: X, Ri, Ro, W1, b1, W2, b2
    const float* X  = (const float*)d_in[0];
    const float* Ri = (const float*)d_in[1];
    const float* Ro = (const float*)d_in[2];
    const float* W1 = (const float*)d_in[3];
    const float* b1 = (const float*)d_in[4];
    const float* W2 = (const float*)d_in[5];
    const float* b2 = (const float*)d_in[6];
    float* out = (float*)d_out;

    dim3 grid1(EGRPS, S_SEG);              // 32 x 16 = 512 blocks of 256 thr
    edgenet_accum_kernel<<<grid1, A_THREADS>>>(X, Ri, Ro);

    dim3 grid2(N_EDGES / EPB2);            // 512 blocks of 256 thr
    edgenet_mlp_kernel<<<grid2, M_THREADS>>>(W1, b1, W2, b2, out);
}